// round 1
// baseline (speedup 1.0000x reference)
#include <cuda_runtime.h>
#include <cstdint>

#define B_ 8
#define S_ 2048
#define D_ 1024
#define DS_ 128
#define MROWS (B_*S_)   // 16384

// ---------------- scratch (static device globals; no allocation) -------------
__device__ float g_k[MROWS*DS_];
__device__ float g_v[MROWS*DS_];
__device__ float g_q[MROWS*DS_];
__device__ float g_a[MROWS*DS_];
__device__ float g_y[MROWS*DS_];

// ---------------- packed fp32x2 helpers (FFMA2 path) -------------------------
typedef unsigned long long u64;

__device__ __forceinline__ u64 pk2(float lo, float hi) {
    u64 r; asm("mov.b64 %0,{%1,%2};" : "=l"(r) : "f"(lo), "f"(hi)); return r;
}
__device__ __forceinline__ float2 up2(u64 v) {
    float2 r; asm("mov.b64 {%0,%1}, %2;" : "=f"(r.x), "=f"(r.y) : "l"(v)); return r;
}
__device__ __forceinline__ u64 ffma2(u64 a, u64 b, u64 c) {
    u64 d; asm("fma.rn.f32x2 %0,%1,%2,%3;" : "=l"(d) : "l"(a), "l"(b), "l"(c)); return d;
}
__device__ __forceinline__ u64 fmul2(u64 a, u64 b) {
    u64 d; asm("mul.rn.f32x2 %0,%1,%2;" : "=l"(d) : "l"(a), "l"(b)); return d;
}
__device__ __forceinline__ u64 fadd2(u64 a, u64 b) {
    u64 d; asm("add.rn.f32x2 %0,%1,%2;" : "=l"(d) : "l"(a), "l"(b)); return d;
}

// =============================================================================
// Kernel 1: input projections. O = X @ W^T with per-variant epilogue.
//   blockIdx.y: 0 -> k (l2norm), 1 -> q (l2norm), 2 -> v (none), 3 -> alpha
// Tile: BM=64, BN=128(full), BK=16, 256 threads, micro-tile 8x4.
// =============================================================================
__global__ __launch_bounds__(256) void proj_kernel(
    const float* __restrict__ x,
    const float* __restrict__ Wk, const float* __restrict__ Wv,
    const float* __restrict__ Wq, const float* __restrict__ Waw,
    const float* __restrict__ Wab, const float* __restrict__ lam)
{
    const int which = blockIdx.y;
    const float* W; float* O; int epi;
    if (which == 0)      { W = Wk;  O = g_k; epi = 1; }
    else if (which == 1) { W = Wq;  O = g_q; epi = 1; }
    else if (which == 2) { W = Wv;  O = g_v; epi = 0; }
    else                 { W = Waw; O = g_a; epi = 2; }

    __shared__ __align__(16) float sX[16][68];
    __shared__ __align__(16) float sW[16][132];

    const int tid = threadIdx.x;
    const int tx  = tid & 31;   // 32 col-groups (one warp per row-group)
    const int ty  = tid >> 5;   // 8 row-groups
    const int m0  = blockIdx.x * 64;

    float acc[8][4];
#pragma unroll
    for (int i = 0; i < 8; i++)
#pragma unroll
        for (int j = 0; j < 4; j++) acc[i][j] = 0.f;

    const int lxr = tid >> 2;          // x-load: row within tile
    const int lxk = (tid & 3) * 4;     // x-load: k offset

    for (int kc = 0; kc < D_; kc += 16) {
        float4 xv = *(const float4*)&x[(size_t)(m0 + lxr) * D_ + kc + lxk];
        int n0a = tid >> 2, k0a = (tid & 3) * 4;
        float4 wv0 = *(const float4*)&W[(size_t)n0a * D_ + kc + k0a];
        int idx2 = tid + 256;
        int n0b = idx2 >> 2, k0b = (idx2 & 3) * 4;
        float4 wv1 = *(const float4*)&W[(size_t)n0b * D_ + kc + k0b];

        __syncthreads();
        sX[lxk + 0][lxr] = xv.x; sX[lxk + 1][lxr] = xv.y;
        sX[lxk + 2][lxr] = xv.z; sX[lxk + 3][lxr] = xv.w;
        sW[k0a + 0][n0a] = wv0.x; sW[k0a + 1][n0a] = wv0.y;
        sW[k0a + 2][n0a] = wv0.z; sW[k0a + 3][n0a] = wv0.w;
        sW[k0b + 0][n0b] = wv1.x; sW[k0b + 1][n0b] = wv1.y;
        sW[k0b + 2][n0b] = wv1.z; sW[k0b + 3][n0b] = wv1.w;
        __syncthreads();

#pragma unroll
        for (int k = 0; k < 16; k++) {
            float a_[8], b_[4];
#pragma unroll
            for (int i = 0; i < 8; i++) a_[i] = sX[k][ty * 8 + i];
#pragma unroll
            for (int j = 0; j < 4; j++) b_[j] = sW[k][tx * 4 + j];
#pragma unroll
            for (int i = 0; i < 8; i++)
#pragma unroll
                for (int j = 0; j < 4; j++) acc[i][j] = fmaf(a_[i], b_[j], acc[i][j]);
        }
    }

    const int nbase = tx * 4;
    if (epi == 0) {
#pragma unroll
        for (int i = 0; i < 8; i++) {
            float4 o = make_float4(acc[i][0], acc[i][1], acc[i][2], acc[i][3]);
            *(float4*)&O[(size_t)(m0 + ty * 8 + i) * DS_ + nbase] = o;
        }
    } else if (epi == 1) {
#pragma unroll
        for (int i = 0; i < 8; i++) {
            float ss = acc[i][0] * acc[i][0] + acc[i][1] * acc[i][1]
                     + acc[i][2] * acc[i][2] + acc[i][3] * acc[i][3];
#pragma unroll
            for (int off = 16; off; off >>= 1)
                ss += __shfl_xor_sync(0xffffffffu, ss, off);
            float inv = 1.f / fmaxf(sqrtf(ss), 1e-12f);
            float4 o = make_float4(acc[i][0] * inv, acc[i][1] * inv,
                                   acc[i][2] * inv, acc[i][3] * inv);
            *(float4*)&O[(size_t)(m0 + ty * 8 + i) * DS_ + nbase] = o;
        }
    } else {
        float bias[4], loga[4];
#pragma unroll
        for (int j = 0; j < 4; j++) {
            int n = nbase + j;
            bias[j] = Wab[n];
            float sl = 1.f / (1.f + __expf(-lam[n]));
            loga[j] = __logf(sl + 1e-8f);
        }
#pragma unroll
        for (int i = 0; i < 8; i++) {
            float4 o;
            float r0 = 1.f / (1.f + __expf(-(acc[i][0] + bias[0])));
            float r1 = 1.f / (1.f + __expf(-(acc[i][1] + bias[1])));
            float r2 = 1.f / (1.f + __expf(-(acc[i][2] + bias[2])));
            float r3 = 1.f / (1.f + __expf(-(acc[i][3] + bias[3])));
            o.x = __expf(8.f * r0 * loga[0]);
            o.y = __expf(8.f * r1 * loga[1]);
            o.z = __expf(8.f * r2 * loga[2]);
            o.w = __expf(8.f * r3 * loga[3]);
            *(float4*)&O[(size_t)(m0 + ty * 8 + i) * DS_ + nbase] = o;
        }
    }
}

// =============================================================================
// Kernel 2: sequential gated-delta recurrence. One CTA per batch, 128 threads.
// Thread t owns column H[:, t] as 64 packed fp32-pairs in registers.
// =============================================================================
__global__ __launch_bounds__(128, 1) void recurrence_kernel()
{
    const int b = blockIdx.x;
    const int t = threadIdx.x;

    __shared__ __align__(16) float sk[2][DS_];
    __shared__ __align__(16) float sv[2][DS_];
    __shared__ __align__(16) float sq[2][DS_];
    __shared__ __align__(16) float sa[2][DS_];
    __shared__ __align__(16) float sc[DS_];
    __shared__ float red[4];

    u64 h[64];
#pragma unroll
    for (int j = 0; j < 64; j++) h[j] = 0ULL;

    const float* bk = g_k + (size_t)b * S_ * DS_;
    const float* bv = g_v + (size_t)b * S_ * DS_;
    const float* bq = g_q + (size_t)b * S_ * DS_;
    const float* ba = g_a + (size_t)b * S_ * DS_;
    float*       by = g_y + (size_t)b * S_ * DS_;

    sk[0][t] = bk[t]; sv[0][t] = bv[t]; sq[0][t] = bq[t]; sa[0][t] = ba[t];
    __syncthreads();

    int buf = 0;
    for (int step = 0; step < S_; ++step) {
        // prefetch next step's vectors (latency hidden under matvec)
        float nk = 0.f, nv = 0.f, nq = 0.f, na = 0.f;
        if (step + 1 < S_) {
            size_t o = (size_t)(step + 1) * DS_ + t;
            nk = bk[o]; nv = bv[o]; nq = bq[o]; na = ba[o];
        }

        // -------- matvecs: pred = q.H, kproj = k.H (packed, 4 acc chains) ----
        const ulonglong2* q4 = (const ulonglong2*)&sq[buf][0];
        const ulonglong2* k4 = (const ulonglong2*)&sk[buf][0];
        u64 p2a = 0, p2b = 0, kp2a = 0, kp2b = 0;
#pragma unroll
        for (int jj = 0; jj < 32; jj++) {
            ulonglong2 qA = q4[jj];
            ulonglong2 kA = k4[jj];
            p2a  = ffma2(qA.x, h[2 * jj],     p2a);
            kp2a = ffma2(kA.x, h[2 * jj],     kp2a);
            p2b  = ffma2(qA.y, h[2 * jj + 1], p2b);
            kp2b = ffma2(kA.y, h[2 * jj + 1], kp2b);
        }
        float2 pp = up2(fadd2(p2a, p2b));
        float pred = pp.x + pp.y;
        float2 kk2 = up2(fadd2(kp2a, kp2b));
        float kpv = kk2.x + kk2.y;

        float myv = sv[buf][t];
        float dv  = myv - kpv;
        float e   = myv - pred; e *= e;
#pragma unroll
        for (int off = 16; off; off >>= 1)
            e += __shfl_xor_sync(0xffffffffu, e, off);
        if ((t & 31) == 0) red[t >> 5] = e;
        __syncthreads();   // barrier A

        float err = (red[0] + red[1]) + (red[2] + red[3]);
        float sur = 1.f / (1.f + __expf(-err * (1.f / 1.000001f)));
        sc[t] = (1.f - sa[buf][t]) * sur * sk[buf][t];

        // stash prefetched step into the other buffer (covered by barrier B)
        int nb = buf ^ 1;
        if (step + 1 < S_) {
            sk[nb][t] = nk; sv[nb][t] = nv; sq[nb][t] = nq; sa[nb][t] = na;
        }
        __syncthreads();   // barrier B

        // -------- update H and accumulate y = q . H_new ----------------------
        const ulonglong2* a4 = (const ulonglong2*)&sa[buf][0];
        const ulonglong2* c4 = (const ulonglong2*)&sc[0];
        u64 dv2 = pk2(dv, dv);
        u64 y2a = 0, y2b = 0;
#pragma unroll
        for (int jj = 0; jj < 32; jj++) {
            ulonglong2 aA = a4[jj];
            ulonglong2 cA = c4[jj];
            ulonglong2 qA = q4[jj];
            u64 t0 = fmul2(cA.x, dv2);
            h[2 * jj] = ffma2(aA.x, h[2 * jj], t0);
            y2a = ffma2(qA.x, h[2 * jj], y2a);
            u64 t1 = fmul2(cA.y, dv2);
            h[2 * jj + 1] = ffma2(aA.y, h[2 * jj + 1], t1);
            y2b = ffma2(qA.y, h[2 * jj + 1], y2b);
        }
        float2 yy = up2(fadd2(y2a, y2b));
        by[(size_t)step * DS_ + t] = yy.x + yy.y;

        buf = nb;
    }
}

// =============================================================================
// Kernel 3: fused RMSNorm(y) * norm_weight, then @ W_o^T.
// Tile: BM=64 rows, BN=128 of D, K=128 full (chunks of 16). 256 threads, 8x4.
// =============================================================================
__global__ __launch_bounds__(256) void out_kernel(
    const float* __restrict__ Wo, const float* __restrict__ nw,
    float* __restrict__ out)
{
    __shared__ __align__(16) float sY[128][68];   // [k][m]
    __shared__ __align__(16) float sW[16][132];   // [k][n]
    __shared__ float sScale[64];
    __shared__ float snw[128];

    const int tid = threadIdx.x;
    const int tx = tid & 31, ty = tid >> 5;
    const int m0 = blockIdx.x * 64, n0 = blockIdx.y * 128;

    if (tid < 128) snw[tid] = nw[tid];

    // load y tile [64 rows x 128 k], transposed into sY[k][m]
#pragma unroll
    for (int it = 0; it < 8; it++) {
        int idx = tid + it * 256;
        int row = idx >> 5;
        int k4  = (idx & 31) * 4;
        float4 v = *(const float4*)&g_y[(size_t)(m0 + row) * DS_ + k4];
        sY[k4 + 0][row] = v.x; sY[k4 + 1][row] = v.y;
        sY[k4 + 2][row] = v.z; sY[k4 + 3][row] = v.w;
    }
    __syncthreads();

    // per-row rms scale (4 threads per row)
    {
        int row = tid >> 2, part = tid & 3;
        float ss = 0.f;
#pragma unroll
        for (int kkk = 0; kkk < 32; kkk++) {
            float v = sY[part * 32 + kkk][row];
            ss = fmaf(v, v, ss);
        }
        ss += __shfl_xor_sync(0xffffffffu, ss, 1);
        ss += __shfl_xor_sync(0xffffffffu, ss, 2);
        if (part == 0) sScale[row] = rsqrtf(ss * (1.f / 128.f) + 1e-6f);
    }
    __syncthreads();

    // rescale y tile in place
    for (int idx = tid; idx < 128 * 64; idx += 256) {
        int k = idx >> 6, m = idx & 63;
        sY[k][m] *= sScale[m];
    }

    float acc[8][4];
#pragma unroll
    for (int i = 0; i < 8; i++)
#pragma unroll
        for (int j = 0; j < 4; j++) acc[i][j] = 0.f;

    for (int kc = 0; kc < DS_; kc += 16) {
        int n0a = tid >> 2, k0a = (tid & 3) * 4;
        float4 w0 = *(const float4*)&Wo[(size_t)(n0 + n0a) * DS_ + kc + k0a];
        int idx2 = tid + 256;
        int n0b = idx2 >> 2, k0b = (idx2 & 3) * 4;
        float4 w1 = *(const float4*)&Wo[(size_t)(n0 + n0b) * DS_ + kc + k0b];

        __syncthreads();
        sW[k0a + 0][n0a] = w0.x * snw[kc + k0a + 0];
        sW[k0a + 1][n0a] = w0.y * snw[kc + k0a + 1];
        sW[k0a + 2][n0a] = w0.z * snw[kc + k0a + 2];
        sW[k0a + 3][n0a] = w0.w * snw[kc + k0a + 3];
        sW[k0b + 0][n0b] = w1.x * snw[kc + k0b + 0];
        sW[k0b + 1][n0b] = w1.y * snw[kc + k0b + 1];
        sW[k0b + 2][n0b] = w1.z * snw[kc + k0b + 2];
        sW[k0b + 3][n0b] = w1.w * snw[kc + k0b + 3];
        __syncthreads();

#pragma unroll
        for (int k = 0; k < 16; k++) {
            float a_[8], b_[4];
#pragma unroll
            for (int i = 0; i < 8; i++) a_[i] = sY[kc + k][ty * 8 + i];
#pragma unroll
            for (int j = 0; j < 4; j++) b_[j] = sW[k][tx * 4 + j];
#pragma unroll
            for (int i = 0; i < 8; i++)
#pragma unroll
                for (int j = 0; j < 4; j++) acc[i][j] = fmaf(a_[i], b_[j], acc[i][j]);
        }
    }

#pragma unroll
    for (int i = 0; i < 8; i++) {
        float4 o = make_float4(acc[i][0], acc[i][1], acc[i][2], acc[i][3]);
        *(float4*)&out[(size_t)(m0 + ty * 8 + i) * D_ + n0 + tx * 4] = o;
    }
}

// =============================================================================
extern "C" void kernel_launch(void* const* d_in, const int* in_sizes, int n_in,
                              void* d_out, int out_size)
{
    const float* x   = (const float*)d_in[0];
    const float* Wk  = (const float*)d_in[1];
    const float* Wv  = (const float*)d_in[2];
    const float* Wq  = (const float*)d_in[3];
    const float* Waw = (const float*)d_in[4];
    const float* Wab = (const float*)d_in[5];
    const float* lam = (const float*)d_in[6];
    const float* Wo  = (const float*)d_in[7];
    const float* nw  = (const float*)d_in[8];
    float* out = (float*)d_out;

    dim3 g1(MROWS / 64, 4);
    proj_kernel<<<g1, 256>>>(x, Wk, Wv, Wq, Waw, Wab, lam);

    recurrence_kernel<<<B_, 128>>>();

    dim3 g3(MROWS / 64, D_ / 128);
    out_kernel<<<g3, 256>>>(Wo, nw, out);
}